// round 11
// baseline (speedup 1.0000x reference)
#include <cuda_runtime.h>
#include <cstdint>
#include <cstddef>
#include <vector>
#include <algorithm>

#define DIMS 256
#define N_ITERS 100
#define RPT 64                  // rows per tile (n = 3125 * 64 exactly)
#define PITCH4 65               // float4 per row (64 data + 1 pad) -> conflict-free
#define TILE4 (RPT * PITCH4)    // 4160 float4 = 66,560 B
#define TPB 128

// ---------------- device state ----------------
__device__ __align__(16) float g_c[2][DIMS];
__device__ float  g_q[2];
__device__ double g_sum1[DIMS];
__device__ double g_tot[DIMS];
__device__ unsigned long long g_cnt1;
__device__ float  g_xsq[262144];

// ---------------- x_sq: XLA row-reduce, float2 pattern (bit-exact, DO NOT TOUCH) ----
__global__ void xsq_kernel(const float* __restrict__ x, int n) {
    int row  = blockIdx.x * (blockDim.x >> 5) + (threadIdx.x >> 5);
    int lane = threadIdx.x & 31;
    if (row >= n) return;
    const float2* xr = (const float2*)(x + (size_t)row * DIMS);
    float acc = 0.f;
    #pragma unroll
    for (int j = 0; j < 4; j++) {
        float2 v = xr[lane + 32 * j];
        acc = __fadd_rn(acc, __fmul_rn(v.x, v.x));
        acc = __fadd_rn(acc, __fmul_rn(v.y, v.y));
    }
    #pragma unroll
    for (int o = 16; o > 0; o >>= 1)
        acc = __fadd_rn(acc, __shfl_xor_sync(0xffffffffu, acc, o));
    if (lane == 0) g_xsq[row] = acc;
}

__device__ __forceinline__ void q_from_centers(int d) {
    if (d < 64) {
        int w = d >> 5, lane = d & 31;
        const float2* cr = (const float2*)g_c[w];
        float acc = 0.f;
        #pragma unroll
        for (int j = 0; j < 4; j++) {
            float2 v = cr[lane + 32 * j];
            acc = __fadd_rn(acc, __fmul_rn(v.x, v.x));
            acc = __fadd_rn(acc, __fmul_rn(v.y, v.y));
        }
        #pragma unroll
        for (int o = 16; o > 0; o >>= 1)
            acc = __fadd_rn(acc, __shfl_xor_sync(0xffffffffu, acc, o));
        if (lane == 0) g_q[w] = acc;
    }
}

__global__ void init_kernel(const float* __restrict__ x, int i0, int i1) {
    int d = threadIdx.x;
    g_c[0][d] = x[(size_t)i0 * DIMS + d];
    g_c[1][d] = x[(size_t)i1 * DIMS + d];
    g_sum1[d] = 0.0;
    g_tot[d]  = 0.0;
    if (d == 0) g_cnt1 = 0ull;
    __syncthreads();
    q_from_centers(d);
}

// per-column double totals (once per launch; order-free)
__global__ void tot_kernel(const float* __restrict__ x, int n) {
    int c = threadIdx.x;
    double acc = 0.0;
    for (int r = blockIdx.x; r < n; r += gridDim.x)
        acc += (double)x[(size_t)r * DIMS + c];
    atomicAdd(&g_tot[c], acc);
}

// ---------------- small-block assign: HW overlaps 3 blocks/SM ----------------
extern __shared__ float4 s4[];   // TILE4 float4
__global__ __launch_bounds__(TPB, 3) void assign_kernel(const float* __restrict__ x, int n) {
    __shared__ float4 c04[64], c14[64];
    __shared__ float4 spart[64];        // upper-half partial sums
    __shared__ unsigned smask[2];

    const int tid = threadIdx.x, lane = tid & 31, wid = tid >> 5;
    const int base  = blockIdx.x * RPT;
    const int valid = min(RPT, n - base);

    // centers into smem (parallel with tile load issue below)
    if (tid < 64)       c04[tid]      = ((const float4*)g_c[0])[tid];
    else                c14[tid - 64] = ((const float4*)g_c[1])[tid - 64];

    // xsq prefetch (independent of tile)
    float xsq = (tid < valid) ? __ldg(&g_xsq[base + tid]) : 0.f;

    // async tile load, row-major, fully coalesced
    uint32_t sbase = (uint32_t)__cvta_generic_to_shared(s4);
    const float4* src = (const float4*)x + (size_t)base * 64;
    const int lim = valid * 64;
    #pragma unroll
    for (int k = 0; k < 32; k++) {
        int e = tid + k * TPB;
        if (e < lim) {
            int r = e >> 6, j = e & 63;
            uint32_t dst = sbase + 16u * (unsigned)(r * PITCH4 + j);
            asm volatile("cp.async.cg.shared.global [%0], [%1], 16;"
                         :: "r"(dst), "l"(src + e) : "memory");
        }
    }
    asm volatile("cp.async.commit_group;" ::: "memory");

    const float q0 = g_q[0], q1 = g_q[1];

    asm volatile("cp.async.wait_group 0;" ::: "memory");
    __syncthreads();

    // ---- dot: threads 0-63, bit-exact serial ascending-k FMA ----
    if (tid < 64) {
        const float4* rp = s4 + tid * PITCH4;
        float s0 = 0.f, s1 = 0.f;
        #pragma unroll 16
        for (int j = 0; j < 64; j++) {
            float4 v  = rp[j];
            float4 c0 = c04[j];
            float4 c1 = c14[j];
            s0 = __fmaf_rn(v.x, c0.x, s0); s1 = __fmaf_rn(v.x, c1.x, s1);
            s0 = __fmaf_rn(v.y, c0.y, s0); s1 = __fmaf_rn(v.y, c1.y, s1);
            s0 = __fmaf_rn(v.z, c0.z, s0); s1 = __fmaf_rn(v.z, c1.z, s1);
            s0 = __fmaf_rn(v.w, c0.w, s0); s1 = __fmaf_rn(v.w, c1.w, s1);
        }
        float d20 = __fadd_rn(__fsub_rn(xsq, __fmul_rn(2.0f, s0)), q0);
        float d21 = __fadd_rn(__fsub_rn(xsq, __fmul_rn(2.0f, s1)), q1);
        bool a1 = (tid < valid) && (d21 < d20);     // argmin, tie -> cluster 0
        unsigned m = __ballot_sync(0xffffffffu, a1);
        if (lane == 0) smask[wid] = m;
    }
    __syncthreads();

    // ---- cluster-1 sums: threads 0-63 rows 0-31, threads 64-127 rows 32-63 ----
    const int half = (tid >= 64);
    const int c4   = tid & 63;
    unsigned m = smask[half];
    const float4* colp = s4 + half * 32 * PITCH4 + c4;
    float aX = 0.f, aY = 0.f, aZ = 0.f, aW = 0.f;
    while (m) {
        int r = __ffs(m) - 1; m &= m - 1;
        float4 v = colp[r * PITCH4];
        aX += v.x; aY += v.y; aZ += v.z; aW += v.w;
    }
    if (half) spart[c4] = make_float4(aX, aY, aZ, aW);
    __syncthreads();
    if (!half) {
        float4 p = spart[c4];
        atomicAdd(&g_sum1[4 * c4 + 0], (double)aX + (double)p.x);
        atomicAdd(&g_sum1[4 * c4 + 1], (double)aY + (double)p.y);
        atomicAdd(&g_sum1[4 * c4 + 2], (double)aZ + (double)p.z);
        atomicAdd(&g_sum1[4 * c4 + 3], (double)aW + (double)p.w);
    }
    if (tid == 0)
        atomicAdd(&g_cnt1, (unsigned long long)(__popc(smask[0]) + __popc(smask[1])));
}

__global__ void update_kernel(int n) {
    int d = threadIdx.x;
    unsigned long long c1n = g_cnt1;
    float cnt1f = (float)c1n;                              // exact (<2^24)
    float cnt0f = (float)(long long)((long long)n - (long long)c1n);
    double s1d = g_sum1[d];
    float  s1  = (float)s1d;
    float  s0  = (float)(g_tot[d] - s1d);
    float c0 = (cnt0f > 0.f) ? __fdiv_rn(s0, fmaxf(cnt0f, 1.f)) : g_c[0][d];
    float c1 = (cnt1f > 0.f) ? __fdiv_rn(s1, fmaxf(cnt1f, 1.f)) : g_c[1][d];
    __syncthreads();
    g_c[0][d] = c0; g_c[1][d] = c1;
    g_sum1[d] = 0.0;
    __syncthreads();
    q_from_centers(d);
    if (d == 0) g_cnt1 = 0ull;
}

__global__ void output_kernel(float* __restrict__ out, int n) {
    int d = threadIdx.x;
    unsigned long long c1n = g_cnt1;
    float mean = __fdiv_rn((float)c1n, (float)n);
    int maj = (mean > 0.5f) ? 1 : 0;
    float cm  = maj ? (float)c1n : (float)(long long)((long long)n - (long long)c1n);
    float cnt = fmaxf(cm, 1.0f);
    double s  = maj ? g_sum1[d] : (g_tot[d] - g_sum1[d]);
    out[d] = __fdiv_rn((float)s, cnt);
}

// ---------------- host: JAX threefry (partitionable/foldlike) init ----------------
static inline uint32_t rotl32(uint32_t v, int r) { return (v << r) | (v >> (32 - r)); }

static void tf2x32(uint32_t k0, uint32_t k1, uint32_t x0, uint32_t x1,
                   uint32_t* o0, uint32_t* o1) {
    uint32_t ks2 = k0 ^ k1 ^ 0x1BD11BDAu;
    x0 += k0; x1 += k1;
    static const int R0[4] = {13, 15, 26, 6};
    static const int R1[4] = {17, 29, 16, 24};
#define TF_RND(r) { x0 += x1; x1 = rotl32(x1, (r)); x1 ^= x0; }
    for (int i = 0; i < 4; i++) TF_RND(R0[i]);  x0 += k1;  x1 += ks2 + 1u;
    for (int i = 0; i < 4; i++) TF_RND(R1[i]);  x0 += ks2; x1 += k0 + 2u;
    for (int i = 0; i < 4; i++) TF_RND(R0[i]);  x0 += k0;  x1 += k1 + 3u;
    for (int i = 0; i < 4; i++) TF_RND(R1[i]);  x0 += k1;  x1 += ks2 + 4u;
    for (int i = 0; i < 4; i++) TF_RND(R0[i]);  x0 += ks2; x1 += k0 + 5u;
#undef TF_RND
    *o0 = x0; *o1 = x1;
}

static void init_indices(int n, int* pi0, int* pi1) {
    uint32_t K0, K1, S0, S1, T0, T1;
    tf2x32(0u, 42u, 0u, 0u, &K0, &K1);
    tf2x32(0u, 42u, 0u, 1u, &S0, &S1);
    tf2x32(K0, K1, 0u, 1u, &T0, &T1);

    std::vector<uint32_t> k1v((size_t)n), k2v((size_t)n);
    for (int i = 0; i < n; i++) {
        uint32_t a, b;
        tf2x32(S0, S1, 0u, (uint32_t)i, &a, &b); k1v[i] = a ^ b;
        tf2x32(T0, T1, 0u, (uint32_t)i, &a, &b); k2v[i] = a ^ b;
    }
    long q0 = -1, q1 = -1;
    for (int p = 0; p < n; p++) {
        uint32_t v = k2v[p];
        if (q0 < 0 || v < k2v[q0]) { q1 = q0; q0 = p; }
        else if (q1 < 0 || v < k2v[q1]) { q1 = p; }
    }
    std::vector<int> idx((size_t)n);
    for (int i = 0; i < n; i++) idx[i] = i;
    std::stable_sort(idx.begin(), idx.end(),
                     [&](int a, int b) { return k1v[a] < k1v[b]; });
    *pi0 = idx[q0];
    *pi1 = idx[q1];
}

// ---------------- entry ----------------
extern "C" void kernel_launch(void* const* d_in, const int* in_sizes, int n_in,
                              void* d_out, int out_size) {
    const float* x = (const float*)d_in[0];
    const int n = in_sizes[0] / DIMS;

    int i0 = 0, i1 = 1;
    init_indices(n, &i0, &i1);

    const int smem_bytes = TILE4 * 16;   // 66,560 B dynamic
    static bool attr_set = false;
    if (!attr_set) {
        cudaFuncSetAttribute(assign_kernel,
                             cudaFuncAttributeMaxDynamicSharedMemorySize, smem_bytes);
        attr_set = true;
    }

    const int ntiles = (n + RPT - 1) / RPT;   // 3125

    init_kernel<<<1, DIMS>>>(x, i0, i1);
    xsq_kernel<<<(n + 7) / 8, 256>>>(x, n);
    tot_kernel<<<592, DIMS>>>(x, n);
    for (int t = 0; t < N_ITERS; t++) {
        assign_kernel<<<ntiles, TPB, smem_bytes>>>(x, n);
        if (t < N_ITERS - 1) update_kernel<<<1, DIMS>>>(n);
    }
    output_kernel<<<1, DIMS>>>((float*)d_out, n);
}

// round 13
// speedup vs baseline: 2.2471x; 2.2471x over previous
#include <cuda_runtime.h>
#include <cstdint>
#include <cstddef>
#include <vector>
#include <algorithm>

#define DIMS 256
#define N_ITERS 100
#define RPB 96            // rows per tile
#define TPB 96
#define NB 148            // persistent blocks = SMs
#define PITCH4 65         // float4 per row (padded) -> 260 words, conflict-free
#define TILE4 (RPB * PITCH4)

// ---------------- device state ----------------
__device__ __align__(16) float g_c[2][DIMS];
__device__ float  g_q[2];
__device__ double g_sum1[DIMS];
__device__ double g_tot[DIMS];
__device__ unsigned long long g_cnt1;
__device__ unsigned long long g_cnt1_prev;
__device__ int    g_done;
__device__ float  g_xsq[262144];

// ---------------- x_sq: XLA row-reduce, float2 pattern (bit-exact, DO NOT TOUCH) ----
__global__ void xsq_kernel(const float* __restrict__ x, int n) {
    int row  = blockIdx.x * (blockDim.x >> 5) + (threadIdx.x >> 5);
    int lane = threadIdx.x & 31;
    if (row >= n) return;
    const float2* xr = (const float2*)(x + (size_t)row * DIMS);
    float acc = 0.f;
    #pragma unroll
    for (int j = 0; j < 4; j++) {
        float2 v = xr[lane + 32 * j];
        acc = __fadd_rn(acc, __fmul_rn(v.x, v.x));
        acc = __fadd_rn(acc, __fmul_rn(v.y, v.y));
    }
    #pragma unroll
    for (int o = 16; o > 0; o >>= 1)
        acc = __fadd_rn(acc, __shfl_xor_sync(0xffffffffu, acc, o));
    if (lane == 0) g_xsq[row] = acc;
}

__device__ __forceinline__ void q_from_centers(int d) {
    if (d < 64) {
        int w = d >> 5, lane = d & 31;
        const float2* cr = (const float2*)g_c[w];
        float acc = 0.f;
        #pragma unroll
        for (int j = 0; j < 4; j++) {
            float2 v = cr[lane + 32 * j];
            acc = __fadd_rn(acc, __fmul_rn(v.x, v.x));
            acc = __fadd_rn(acc, __fmul_rn(v.y, v.y));
        }
        #pragma unroll
        for (int o = 16; o > 0; o >>= 1)
            acc = __fadd_rn(acc, __shfl_xor_sync(0xffffffffu, acc, o));
        if (lane == 0) g_q[w] = acc;
    }
}

__global__ void init_kernel(const float* __restrict__ x, int i0, int i1) {
    int d = threadIdx.x;
    g_c[0][d] = x[(size_t)i0 * DIMS + d];
    g_c[1][d] = x[(size_t)i1 * DIMS + d];
    g_sum1[d] = 0.0;
    g_tot[d]  = 0.0;
    if (d == 0) { g_cnt1 = 0ull; g_cnt1_prev = 0xFFFFFFFFFFFFFFFFull; g_done = 0; }
    __syncthreads();
    q_from_centers(d);
}

// per-column double totals (once per launch; order-free)
__global__ void tot_kernel(const float* __restrict__ x, int n) {
    int c = threadIdx.x;
    double acc = 0.0;
    for (int r = blockIdx.x; r < n; r += gridDim.x)
        acc += (double)x[(size_t)r * DIMS + c];
    atomicAdd(&g_tot[c], acc);
}

// ---------------- persistent double-buffered assign + cluster1 sum (R9 structure) ----
extern __shared__ float4 s4[];
__global__ __launch_bounds__(TPB, 1) void assign_kernel(const float* __restrict__ x, int n) {
    if (g_done) return;                // converged: this launch is a no-op

    float4* bufs = s4;                 // 2 * TILE4
    float4* c04  = s4 + 2 * TILE4;     // 64
    float4* c14  = c04 + 64;           // 64
    __shared__ unsigned sm_m1[3];

    const int tid = threadIdx.x, lane = tid & 31, w = tid >> 5;

    for (int i = tid; i < 64; i += TPB) {
        c04[i] = ((const float4*)g_c[0])[i];
        c14[i] = ((const float4*)g_c[1])[i];
    }
    const float q0 = g_q[0], q1 = g_q[1];
    const int ngroups = (n + RPB - 1) / RPB;

    uint32_t sbase = (uint32_t)__cvta_generic_to_shared(bufs);

    double aX = 0, aY = 0, aZ = 0, aW = 0;
    unsigned long long myCnt = 0;

    auto issue_tile = [&](int g, int b) {
        int base  = g * RPB;
        int valid = min(RPB, n - base);
        int tot4  = valid * 64;
        const float4* src = (const float4*)(x + (size_t)base * DIMS);
        for (int e = tid; e < tot4; e += TPB) {
            int r = e >> 6, j = e & 63;
            uint32_t dst = sbase + 16u * (unsigned)(b * TILE4 + r * PITCH4 + j);
            asm volatile("cp.async.cg.shared.global [%0], [%1], 16;"
                         :: "r"(dst), "l"(src + e) : "memory");
        }
        asm volatile("cp.async.commit_group;" ::: "memory");
    };

    int g = blockIdx.x;
    issue_tile(g, 0);
    int cur = 0;

    for (; g < ngroups; g += NB) {
        int gn = g + NB;
        if (gn < ngroups) {
            issue_tile(gn, cur ^ 1);
            asm volatile("cp.async.wait_group 1;" ::: "memory");
        } else {
            asm volatile("cp.async.wait_group 0;" ::: "memory");
        }
        __syncthreads();

        const int base  = g * RPB;
        const int valid = min(RPB, n - base);

        float xsq = (tid < valid) ? __ldg(&g_xsq[base + tid]) : 0.f;

        // ---- dot: thread-per-row, bit-exact serial ascending-k FMA ----
        const float4* row = bufs + cur * TILE4 + min(tid, valid - 1) * PITCH4;
        float s0 = 0.f, s1 = 0.f;
        #pragma unroll 16
        for (int j = 0; j < 64; j++) {
            float4 v  = row[j];
            float4 c0 = c04[j];
            float4 c1 = c14[j];
            s0 = __fmaf_rn(v.x, c0.x, s0); s1 = __fmaf_rn(v.x, c1.x, s1);
            s0 = __fmaf_rn(v.y, c0.y, s0); s1 = __fmaf_rn(v.y, c1.y, s1);
            s0 = __fmaf_rn(v.z, c0.z, s0); s1 = __fmaf_rn(v.z, c1.z, s1);
            s0 = __fmaf_rn(v.w, c0.w, s0); s1 = __fmaf_rn(v.w, c1.w, s1);
        }
        float d20 = __fadd_rn(__fsub_rn(xsq, __fmul_rn(2.0f, s0)), q0);
        float d21 = __fadd_rn(__fsub_rn(xsq, __fmul_rn(2.0f, s1)), q1);
        bool a1 = (tid < valid) && (d21 < d20);     // argmin, tie -> cluster 0
        unsigned m1 = __ballot_sync(0xffffffffu, a1);
        if (lane == 0) { sm_m1[w] = m1; myCnt += (unsigned)__popc(m1); }
        __syncthreads();

        // ---- cluster-1 column sums: tid<64, float4 column-group, mask-skip ----
        if (tid < 64) {
            const float4* col = bufs + cur * TILE4 + tid;
            float pX = 0.f, pY = 0.f, pZ = 0.f, pW = 0.f;
            #pragma unroll
            for (int blk = 0; blk < 3; blk++) {
                int rbase = blk * 32;
                int rend  = valid - rbase; if (rend > 32) rend = 32;
                if (rend <= 0) break;
                unsigned m = sm_m1[blk];
                for (int r = 0; r < rend; r++) {
                    if ((m >> r) & 1u) {
                        float4 v = col[(rbase + r) * PITCH4];
                        pX += v.x; pY += v.y; pZ += v.z; pW += v.w;
                    }
                }
            }
            aX += (double)pX; aY += (double)pY; aZ += (double)pZ; aW += (double)pW;
        }
        __syncthreads();
        cur ^= 1;
    }

    if (tid < 64) {
        atomicAdd(&g_sum1[4 * tid + 0], aX);
        atomicAdd(&g_sum1[4 * tid + 1], aY);
        atomicAdd(&g_sum1[4 * tid + 2], aZ);
        atomicAdd(&g_sum1[4 * tid + 3], aW);
    }
    if (lane == 0) atomicAdd(&g_cnt1, myCnt);
}

__global__ void update_kernel(int n) {
    if (g_done) return;                // frozen state: keep sums/counts for output
    int d = threadIdx.x;
    unsigned long long c1n = g_cnt1;
    float cnt1f = (float)c1n;                              // exact (<2^24)
    float cnt0f = (float)(long long)((long long)n - (long long)c1n);
    double s1d = g_sum1[d];
    float  s1  = (float)s1d;
    float  s0  = (float)(g_tot[d] - s1d);
    float c0 = (cnt0f > 0.f) ? __fdiv_rn(s0, fmaxf(cnt0f, 1.f)) : g_c[0][d];
    float c1 = (cnt1f > 0.f) ? __fdiv_rn(s1, fmaxf(cnt1f, 1.f)) : g_c[1][d];

    // fixed-point detection: fp32 centers + counts identical => all future
    // iterations are bit-identical no-ops (dot/argmin is a pure function of
    // the fp32 centers). Preserve sums/counts for output_kernel.
    int same = (c0 == g_c[0][d]) && (c1 == g_c[1][d]) && (c1n == g_cnt1_prev);
    int allsame = __syncthreads_and(same);
    if (allsame) { if (d == 0) g_done = 1; return; }

    g_c[0][d] = c0; g_c[1][d] = c1;
    g_sum1[d] = 0.0;
    if (d == 0) g_cnt1_prev = c1n;
    __syncthreads();
    q_from_centers(d);
    if (d == 0) g_cnt1 = 0ull;
}

__global__ void output_kernel(float* __restrict__ out, int n) {
    int d = threadIdx.x;
    unsigned long long c1n = g_cnt1;
    float mean = __fdiv_rn((float)c1n, (float)n);
    int maj = (mean > 0.5f) ? 1 : 0;
    float cm  = maj ? (float)c1n : (float)(long long)((long long)n - (long long)c1n);
    float cnt = fmaxf(cm, 1.0f);
    double s  = maj ? g_sum1[d] : (g_tot[d] - g_sum1[d]);
    out[d] = __fdiv_rn((float)s, cnt);
}

// ---------------- host: JAX threefry (partitionable/foldlike) init ----------------
static inline uint32_t rotl32(uint32_t v, int r) { return (v << r) | (v >> (32 - r)); }

static void tf2x32(uint32_t k0, uint32_t k1, uint32_t x0, uint32_t x1,
                   uint32_t* o0, uint32_t* o1) {
    uint32_t ks2 = k0 ^ k1 ^ 0x1BD11BDAu;
    x0 += k0; x1 += k1;
    static const int R0[4] = {13, 15, 26, 6};
    static const int R1[4] = {17, 29, 16, 24};
#define TF_RND(r) { x0 += x1; x1 = rotl32(x1, (r)); x1 ^= x0; }
    for (int i = 0; i < 4; i++) TF_RND(R0[i]);  x0 += k1;  x1 += ks2 + 1u;
    for (int i = 0; i < 4; i++) TF_RND(R1[i]);  x0 += ks2; x1 += k0 + 2u;
    for (int i = 0; i < 4; i++) TF_RND(R0[i]);  x0 += k0;  x1 += k1 + 3u;
    for (int i = 0; i < 4; i++) TF_RND(R1[i]);  x0 += k1;  x1 += ks2 + 4u;
    for (int i = 0; i < 4; i++) TF_RND(R0[i]);  x0 += ks2; x1 += k0 + 5u;
#undef TF_RND
    *o0 = x0; *o1 = x1;
}

static void init_indices(int n, int* pi0, int* pi1) {
    uint32_t K0, K1, S0, S1, T0, T1;
    tf2x32(0u, 42u, 0u, 0u, &K0, &K1);
    tf2x32(0u, 42u, 0u, 1u, &S0, &S1);
    tf2x32(K0, K1, 0u, 1u, &T0, &T1);

    std::vector<uint32_t> k1v((size_t)n), k2v((size_t)n);
    for (int i = 0; i < n; i++) {
        uint32_t a, b;
        tf2x32(S0, S1, 0u, (uint32_t)i, &a, &b); k1v[i] = a ^ b;
        tf2x32(T0, T1, 0u, (uint32_t)i, &a, &b); k2v[i] = a ^ b;
    }
    long q0 = -1, q1 = -1;
    for (int p = 0; p < n; p++) {
        uint32_t v = k2v[p];
        if (q0 < 0 || v < k2v[q0]) { q1 = q0; q0 = p; }
        else if (q1 < 0 || v < k2v[q1]) { q1 = p; }
    }
    std::vector<int> idx((size_t)n);
    for (int i = 0; i < n; i++) idx[i] = i;
    std::stable_sort(idx.begin(), idx.end(),
                     [&](int a, int b) { return k1v[a] < k1v[b]; });
    *pi0 = idx[q0];
    *pi1 = idx[q1];
}

// ---------------- entry ----------------
extern "C" void kernel_launch(void* const* d_in, const int* in_sizes, int n_in,
                              void* d_out, int out_size) {
    const float* x = (const float*)d_in[0];
    const int n = in_sizes[0] / DIMS;

    int i0 = 0, i1 = 1;
    init_indices(n, &i0, &i1);

    const int smem_bytes = (2 * TILE4 + 128) * 16;   // 201,728 B
    static bool attr_set = false;
    if (!attr_set) {
        cudaFuncSetAttribute(assign_kernel,
                             cudaFuncAttributeMaxDynamicSharedMemorySize, smem_bytes);
        attr_set = true;
    }

    init_kernel<<<1, DIMS>>>(x, i0, i1);
    xsq_kernel<<<(n + 7) / 8, 256>>>(x, n);
    tot_kernel<<<592, DIMS>>>(x, n);
    for (int t = 0; t < N_ITERS; t++) {
        assign_kernel<<<NB, TPB, smem_bytes>>>(x, n);
        if (t < N_ITERS - 1) update_kernel<<<1, DIMS>>>(n);
    }
    output_kernel<<<1, DIMS>>>((float*)d_out, n);
}

// round 14
// speedup vs baseline: 2.5776x; 1.1471x over previous
#include <cuda_runtime.h>
#include <cstdint>
#include <cstddef>
#include <vector>
#include <algorithm>

#define DIMS 256
#define N_ITERS 100
#define RPB 96            // rows per tile
#define TPB 192
#define NB 148            // persistent blocks = SMs
#define PITCH4 65         // float4 per row (padded), conflict-free both phases
#define TILE4 (RPB * PITCH4)

// ---------------- device state ----------------
__device__ __align__(16) float g_c[2][DIMS];
__device__ float  g_q[2];
__device__ double g_sum1[DIMS];
__device__ double g_tot[DIMS];
__device__ unsigned long long g_cnt1;
__device__ unsigned g_arrive;
__device__ float  g_xsq[262144];

// ---------------- x_sq: XLA row-reduce, float2 pattern (bit-exact, DO NOT TOUCH) ----
__global__ void xsq_kernel(const float* __restrict__ x, int n) {
    int row  = blockIdx.x * (blockDim.x >> 5) + (threadIdx.x >> 5);
    int lane = threadIdx.x & 31;
    if (row >= n) return;
    const float2* xr = (const float2*)(x + (size_t)row * DIMS);
    float acc = 0.f;
    #pragma unroll
    for (int j = 0; j < 4; j++) {
        float2 v = xr[lane + 32 * j];
        acc = __fadd_rn(acc, __fmul_rn(v.x, v.x));
        acc = __fadd_rn(acc, __fmul_rn(v.y, v.y));
    }
    #pragma unroll
    for (int o = 16; o > 0; o >>= 1)
        acc = __fadd_rn(acc, __shfl_xor_sync(0xffffffffu, acc, o));
    if (lane == 0) g_xsq[row] = acc;
}

__device__ __forceinline__ void q_from_centers(int d) {
    if (d < 64) {
        int w = d >> 5, lane = d & 31;
        const float2* cr = (const float2*)g_c[w];
        float acc = 0.f;
        #pragma unroll
        for (int j = 0; j < 4; j++) {
            float2 v = cr[lane + 32 * j];
            acc = __fadd_rn(acc, __fmul_rn(v.x, v.x));
            acc = __fadd_rn(acc, __fmul_rn(v.y, v.y));
        }
        #pragma unroll
        for (int o = 16; o > 0; o >>= 1)
            acc = __fadd_rn(acc, __shfl_xor_sync(0xffffffffu, acc, o));
        if (lane == 0) g_q[w] = acc;
    }
}

__global__ void init_kernel(const float* __restrict__ x, int i0, int i1) {
    int d = threadIdx.x;
    g_c[0][d] = x[(size_t)i0 * DIMS + d];
    g_c[1][d] = x[(size_t)i1 * DIMS + d];
    g_sum1[d] = 0.0;
    g_tot[d]  = 0.0;
    if (d == 0) { g_cnt1 = 0ull; g_arrive = 0u; }
    __syncthreads();
    q_from_centers(d);
}

// per-column double totals (once per launch; order-free)
__global__ void tot_kernel(const float* __restrict__ x, int n) {
    int c = threadIdx.x;
    double acc = 0.0;
    for (int r = blockIdx.x; r < n; r += gridDim.x)
        acc += (double)x[(size_t)r * DIMS + c];
    atomicAdd(&g_tot[c], acc);
}

// ---------------- persistent double-buffered assign + fused update ----------------
extern __shared__ float4 s4[];   // 2 * TILE4
__global__ __launch_bounds__(TPB, 1) void assign_kernel(const float* __restrict__ x,
                                                        int n, int do_update) {
    __shared__ float4 c04[64], c14[64];
    __shared__ double sdbl[2][64][4];     // thirds 1,2 partials
    __shared__ unsigned sm_m1[3];
    __shared__ int slast;

    float4* bufs = s4;
    const int tid = threadIdx.x, lane = tid & 31, w = tid >> 5;
    const int c4 = tid & 63, third = tid >> 6;      // sum-phase role

    for (int i = tid; i < 64; i += TPB) {
        c04[i] = ((const float4*)g_c[0])[i];
        c14[i] = ((const float4*)g_c[1])[i];
    }
    const float q0 = g_q[0], q1 = g_q[1];
    const int ngroups = (n + RPB - 1) / RPB;

    uint32_t sbase = (uint32_t)__cvta_generic_to_shared(bufs);

    double aX = 0, aY = 0, aZ = 0, aW = 0;
    unsigned long long myCnt = 0;

    auto issue_tile = [&](int g, int b) {
        int base  = g * RPB;
        int valid = min(RPB, n - base);
        int tot4  = valid * 64;
        const float4* src = (const float4*)(x + (size_t)base * DIMS);
        #pragma unroll
        for (int k = 0; k < 32; k++) {
            int e = tid + k * TPB;
            if (e < tot4) {
                int r = e >> 6, j = e & 63;
                uint32_t dst = sbase + 16u * (unsigned)(b * TILE4 + r * PITCH4 + j);
                asm volatile("cp.async.cg.shared.global [%0], [%1], 16;"
                             :: "r"(dst), "l"(src + e) : "memory");
            }
        }
        asm volatile("cp.async.commit_group;" ::: "memory");
    };

    int g = blockIdx.x;
    issue_tile(g, 0);
    int cur = 0;

    for (; g < ngroups; g += NB) {
        int gn = g + NB;
        if (gn < ngroups) {
            issue_tile(gn, cur ^ 1);
            asm volatile("cp.async.wait_group 1;" ::: "memory");
        } else {
            asm volatile("cp.async.wait_group 0;" ::: "memory");
        }
        __syncthreads();

        const int base  = g * RPB;
        const int valid = min(RPB, n - base);

        // ---- dot: threads 0-95, thread-per-row, bit-exact serial ascending-k FMA ----
        if (tid < RPB) {
            float xsq = (tid < valid) ? __ldg(&g_xsq[base + tid]) : 0.f;
            const float4* row = bufs + cur * TILE4 + min(tid, valid - 1) * PITCH4;
            float s0 = 0.f, s1 = 0.f;
            #pragma unroll 16
            for (int j = 0; j < 64; j++) {
                float4 v  = row[j];
                float4 c0 = c04[j];
                float4 c1 = c14[j];
                s0 = __fmaf_rn(v.x, c0.x, s0); s1 = __fmaf_rn(v.x, c1.x, s1);
                s0 = __fmaf_rn(v.y, c0.y, s0); s1 = __fmaf_rn(v.y, c1.y, s1);
                s0 = __fmaf_rn(v.z, c0.z, s0); s1 = __fmaf_rn(v.z, c1.z, s1);
                s0 = __fmaf_rn(v.w, c0.w, s0); s1 = __fmaf_rn(v.w, c1.w, s1);
            }
            float d20 = __fadd_rn(__fsub_rn(xsq, __fmul_rn(2.0f, s0)), q0);
            float d21 = __fadd_rn(__fsub_rn(xsq, __fmul_rn(2.0f, s1)), q1);
            bool a1 = (tid < valid) && (d21 < d20);     // argmin, tie -> cluster 0
            unsigned m1 = __ballot_sync(0xffffffffu, a1);
            if (lane == 0) { sm_m1[w] = m1; myCnt += (unsigned)__popc(m1); }
        }
        __syncthreads();

        // ---- cluster-1 sums: 192 threads, (col-group, third) each 32 rows, select-FMA ----
        {
            unsigned m = sm_m1[third];
            const float4* colp = bufs + cur * TILE4 + third * 32 * PITCH4 + c4;
            float pX = 0.f, pY = 0.f, pZ = 0.f, pW = 0.f;
            #pragma unroll
            for (int r = 0; r < 32; r++) {
                float ww = ((m >> r) & 1u) ? 1.0f : 0.0f;   // exact weight
                float4 v = colp[r * PITCH4];
                pX = __fmaf_rn(v.x, ww, pX);
                pY = __fmaf_rn(v.y, ww, pY);
                pZ = __fmaf_rn(v.z, ww, pZ);
                pW = __fmaf_rn(v.w, ww, pW);
            }
            aX += (double)pX; aY += (double)pY; aZ += (double)pZ; aW += (double)pW;
        }
        __syncthreads();        // tile consumed before next overwrite
        cur ^= 1;
    }

    // ---- combine thirds, one atomicAdd set per block ----
    if (third > 0) {
        sdbl[third - 1][c4][0] = aX; sdbl[third - 1][c4][1] = aY;
        sdbl[third - 1][c4][2] = aZ; sdbl[third - 1][c4][3] = aW;
    }
    __syncthreads();
    if (third == 0) {
        atomicAdd(&g_sum1[4 * c4 + 0], aX + sdbl[0][c4][0] + sdbl[1][c4][0]);
        atomicAdd(&g_sum1[4 * c4 + 1], aY + sdbl[0][c4][1] + sdbl[1][c4][1]);
        atomicAdd(&g_sum1[4 * c4 + 2], aZ + sdbl[0][c4][2] + sdbl[1][c4][2]);
        atomicAdd(&g_sum1[4 * c4 + 3], aW + sdbl[0][c4][3] + sdbl[1][c4][3]);
    }
    if (tid < RPB && lane == 0) atomicAdd(&g_cnt1, myCnt);

    // ---- last-arriving block performs the center update inline ----
    __threadfence();
    __syncthreads();
    if (tid == 0) slast = (atomicAdd(&g_arrive, 1u) == NB - 1) ? 1 : 0;
    __syncthreads();
    if (!slast) return;

    if (do_update) {
        __threadfence();                              // acquire all blocks' atomics
        unsigned long long c1n = *(volatile unsigned long long*)&g_cnt1;
        float cnt1f = (float)c1n;                     // exact (<2^24)
        float cnt0f = (float)(long long)((long long)n - (long long)c1n);
        for (int d = tid; d < DIMS; d += TPB) {
            double s1d = g_sum1[d];
            float  s1  = (float)s1d;
            float  s0  = (float)(g_tot[d] - s1d);
            float c0 = (cnt0f > 0.f) ? __fdiv_rn(s0, fmaxf(cnt0f, 1.f)) : g_c[0][d];
            float c1 = (cnt1f > 0.f) ? __fdiv_rn(s1, fmaxf(cnt1f, 1.f)) : g_c[1][d];
            g_c[0][d] = c0; g_c[1][d] = c1;
            g_sum1[d] = 0.0;
        }
        __syncthreads();
        q_from_centers(tid);
        if (tid == 0) g_cnt1 = 0ull;
    }
    if (tid == 0) g_arrive = 0u;
}

__global__ void output_kernel(float* __restrict__ out, int n) {
    int d = threadIdx.x;
    unsigned long long c1n = g_cnt1;
    float mean = __fdiv_rn((float)c1n, (float)n);
    int maj = (mean > 0.5f) ? 1 : 0;
    float cm  = maj ? (float)c1n : (float)(long long)((long long)n - (long long)c1n);
    float cnt = fmaxf(cm, 1.0f);
    double s  = maj ? g_sum1[d] : (g_tot[d] - g_sum1[d]);
    out[d] = __fdiv_rn((float)s, cnt);
}

// ---------------- host: JAX threefry (partitionable/foldlike) init ----------------
static inline uint32_t rotl32(uint32_t v, int r) { return (v << r) | (v >> (32 - r)); }

static void tf2x32(uint32_t k0, uint32_t k1, uint32_t x0, uint32_t x1,
                   uint32_t* o0, uint32_t* o1) {
    uint32_t ks2 = k0 ^ k1 ^ 0x1BD11BDAu;
    x0 += k0; x1 += k1;
    static const int R0[4] = {13, 15, 26, 6};
    static const int R1[4] = {17, 29, 16, 24};
#define TF_RND(r) { x0 += x1; x1 = rotl32(x1, (r)); x1 ^= x0; }
    for (int i = 0; i < 4; i++) TF_RND(R0[i]);  x0 += k1;  x1 += ks2 + 1u;
    for (int i = 0; i < 4; i++) TF_RND(R1[i]);  x0 += ks2; x1 += k0 + 2u;
    for (int i = 0; i < 4; i++) TF_RND(R0[i]);  x0 += k0;  x1 += k1 + 3u;
    for (int i = 0; i < 4; i++) TF_RND(R1[i]);  x0 += k1;  x1 += ks2 + 4u;
    for (int i = 0; i < 4; i++) TF_RND(R0[i]);  x0 += ks2; x1 += k0 + 5u;
#undef TF_RND
    *o0 = x0; *o1 = x1;
}

static void init_indices(int n, int* pi0, int* pi1) {
    uint32_t K0, K1, S0, S1, T0, T1;
    tf2x32(0u, 42u, 0u, 0u, &K0, &K1);
    tf2x32(0u, 42u, 0u, 1u, &S0, &S1);
    tf2x32(K0, K1, 0u, 1u, &T0, &T1);

    std::vector<uint32_t> k1v((size_t)n), k2v((size_t)n);
    for (int i = 0; i < n; i++) {
        uint32_t a, b;
        tf2x32(S0, S1, 0u, (uint32_t)i, &a, &b); k1v[i] = a ^ b;
        tf2x32(T0, T1, 0u, (uint32_t)i, &a, &b); k2v[i] = a ^ b;
    }
    long q0 = -1, q1 = -1;
    for (int p = 0; p < n; p++) {
        uint32_t v = k2v[p];
        if (q0 < 0 || v < k2v[q0]) { q1 = q0; q0 = p; }
        else if (q1 < 0 || v < k2v[q1]) { q1 = p; }
    }
    std::vector<int> idx((size_t)n);
    for (int i = 0; i < n; i++) idx[i] = i;
    std::stable_sort(idx.begin(), idx.end(),
                     [&](int a, int b) { return k1v[a] < k1v[b]; });
    *pi0 = idx[q0];
    *pi1 = idx[q1];
}

// ---------------- entry ----------------
extern "C" void kernel_launch(void* const* d_in, const int* in_sizes, int n_in,
                              void* d_out, int out_size) {
    const float* x = (const float*)d_in[0];
    const int n = in_sizes[0] / DIMS;

    int i0 = 0, i1 = 1;
    init_indices(n, &i0, &i1);

    const int smem_bytes = 2 * TILE4 * 16;    // 199,680 B dynamic
    static bool attr_set = false;
    if (!attr_set) {
        cudaFuncSetAttribute(assign_kernel,
                             cudaFuncAttributeMaxDynamicSharedMemorySize, smem_bytes);
        attr_set = true;
    }

    init_kernel<<<1, DIMS>>>(x, i0, i1);
    xsq_kernel<<<(n + 7) / 8, 256>>>(x, n);
    tot_kernel<<<592, DIMS>>>(x, n);
    for (int t = 0; t < N_ITERS; t++)
        assign_kernel<<<NB, TPB, smem_bytes>>>(x, n, (t < N_ITERS - 1) ? 1 : 0);
    output_kernel<<<1, DIMS>>>((float*)d_out, n);
}